// round 15
// baseline (speedup 1.0000x reference)
#include <cuda_runtime.h>
#include <cuda_fp16.h>

#define NNODES 100000
#define DIM 128
#define FIN 64
#define SAMP 16

// Scratch (module-load allocated; no runtime alloc)
__device__ __half g_z  [(size_t)NNODES * DIM];   // layer-1 pre-aggregation
__device__ __half g_x1h[(size_t)NNODES * DIM];   // layer-1 output (fp16)
__device__ float  g_wc [DIM * FIN];              // folded w1 @ wf

// ---------------------------------------------------------------------------
// wc = w1 @ wf   [128,128]@[128,64] -> [128,64]
// ---------------------------------------------------------------------------
__global__ void wc_kernel(const float* __restrict__ w1,
                          const float* __restrict__ wf,
                          float* __restrict__ wc)
{
    int idx = blockIdx.x * 256 + threadIdx.x;      // 8192 outputs
    if (idx >= DIM * FIN) return;
    int i = idx >> 6, j = idx & 63;
    float s = 0.0f;
    #pragma unroll 8
    for (int t = 0; t < DIM; t++)
        s = fmaf(w1[i * DIM + t], wf[t * FIN + j], s);
    wc[i * FIN + j] = s;
}

// ---------------------------------------------------------------------------
// Common PTX helpers
// ---------------------------------------------------------------------------
#define MMA_F16(D, A0,A1,A2,A3, B0,B1)                                       \
    asm volatile("mma.sync.aligned.m16n8k16.row.col.f32.f16.f16.f32 "        \
                 "{%0,%1,%2,%3},{%4,%5,%6,%7},{%8,%9},{%0,%1,%2,%3};"        \
                 : "+f"(D[0]), "+f"(D[1]), "+f"(D[2]), "+f"(D[3])            \
                 : "r"(A0), "r"(A1), "r"(A2), "r"(A3), "r"(B0), "r"(B1))

#define LDSM_X4(R0,R1,R2,R3, ADDR)                                           \
    asm volatile("ldmatrix.sync.aligned.m8n8.x4.shared.b16 {%0,%1,%2,%3}, [%4];" \
                 : "=r"(R0), "=r"(R1), "=r"(R2), "=r"(R3) : "r"(ADDR))

#define EPI_STRIDE 272          // fp16 epilogue smem row stride (bytes)
#define EPI_BYTES  (8 * 16 * EPI_STRIDE)   // 34816 B

// ---------------------------------------------------------------------------
// Dense GEMM (layer-1 / K=64 only): z[nrows,128](fp16) = A(fp32) @ W^T
// fp32 A converted while staging; ldmatrix + paired-W MMA; smem epilogue.
// ---------------------------------------------------------------------------
template<int K>
__global__ __launch_bounds__(256, 3)
void gemm_tc(const float* __restrict__ Av,
             const float* __restrict__ W,
             __half* __restrict__ C, int nrows)
{
    constexpr int P   = K / 4;
    constexpr int PM  = P - 1;
    constexpr int CH  = K / 8;
    constexpr int CHM = CH - 1;

    extern __shared__ char smraw[];
    uint2* WP  = (uint2*)smraw;                           // [DIM][P]
    char*  EPI = smraw + (size_t)DIM * P * sizeof(uint2);
    uint4* AS  = (uint4*)EPI;                             // [128][CH] swizzled

    const int tid = threadIdx.x;
    const int rowbase = blockIdx.x * 128;

    for (int idx = tid; idx < 128 * CH; idx += 256) {
        int r = idx / CH, ch = idx % CH;
        int gr = rowbase + r;
        if (gr >= nrows) gr = nrows - 1;
        const float* src = Av + (size_t)gr * K + ch * 8;
        __half2 h0 = __float22half2_rn(*(const float2*)&src[0]);
        __half2 h1 = __float22half2_rn(*(const float2*)&src[2]);
        __half2 h2 = __float22half2_rn(*(const float2*)&src[4]);
        __half2 h3 = __float22half2_rn(*(const float2*)&src[6]);
        AS[r * CH + (ch ^ ((r & 7) & CHM))] =
            make_uint4(*(unsigned*)&h0, *(unsigned*)&h1,
                       *(unsigned*)&h2, *(unsigned*)&h3);
    }
    for (int idx = tid; idx < DIM * P; idx += 256) {
        int n = idx / P, p = idx % P;
        int ks = p >> 2, c = p & 3;
        const float* row = W + n * K + ks * 16 + 2 * c;
        __half2 h0 = __float22half2_rn(*(const float2*)&row[0]);
        __half2 h1 = __float22half2_rn(*(const float2*)&row[8]);
        int sp = p ^ (((n & 7) << 2) & PM);
        WP[n * P + sp] = make_uint2(*(unsigned*)&h0, *(unsigned*)&h1);
    }
    __syncthreads();

    const int warp = tid >> 5, lane = tid & 31;
    const int g = lane >> 2, c = lane & 3;
    const int slab = warp * 16;
    const int lrow = slab + (lane & 7) + ((lane >> 3) & 1) * 8;
    const int lhi  = lane >> 4;
    const int lsw  = (lrow & 7) & CHM;
    const unsigned as_u32 =
        (unsigned)__cvta_generic_to_shared(AS) + (unsigned)(lrow * CH) * 16u;

    float d[16][4];
    #pragma unroll
    for (int nt = 0; nt < 16; nt++)
        #pragma unroll
        for (int q = 0; q < 4; q++) d[nt][q] = 0.0f;

    const int gswm = (g << 2) & PM;

    #pragma unroll
    for (int ks = 0; ks < K / 16; ks++) {
        unsigned a0, a1, a2, a3;
        unsigned ad = as_u32 + (unsigned)(((ks * 2 + lhi) ^ lsw) * 16);
        LDSM_X4(a0, a1, a2, a3, ad);
        const int col = (ks * 4 + c) ^ gswm;
        #pragma unroll
        for (int nt = 0; nt < 16; nt++) {
            uint2 b = WP[(nt * 8 + g) * P + col];
            MMA_F16(d[nt], a0, a1, a2, a3, b.x, b.y);
        }
    }
    __syncthreads();

    char* myepi = EPI + warp * (16 * EPI_STRIDE);
    #pragma unroll
    for (int nt = 0; nt < 16; nt++) {
        __half2 h0 = __float22half2_rn(make_float2(d[nt][0], d[nt][1]));
        __half2 h1 = __float22half2_rn(make_float2(d[nt][2], d[nt][3]));
        *(__half2*)(myepi + g * EPI_STRIDE + nt * 16 + 4 * c) = h0;
        *(__half2*)(myepi + (g + 8) * EPI_STRIDE + nt * 16 + 4 * c) = h1;
    }
    __syncwarp();
    {
        const int rr = lane >> 4;
        const int j  = lane & 15;
        #pragma unroll
        for (int i = 0; i < 8; i++) {
            int r = i * 2 + rr;
            uint4 v = *(const uint4*)(myepi + r * EPI_STRIDE + j * 16);
            int gr = rowbase + slab + r;
            if (gr < nrows)
                *(uint4*)((char*)(C + (size_t)gr * DIM) + j * 16) = v;
        }
    }
}

// ---------------------------------------------------------------------------
// gathernorm (layer 1): x1[n] = normalize(relu((z[n]+sum z[nb])/17)) -> fp16
// 16 lanes/node; fp16 pairwise tree + fp32 group accumulation.
// ---------------------------------------------------------------------------
__global__ __launch_bounds__(256)
void gathernorm(const __half* __restrict__ z,
                const int*    __restrict__ nb,
                __half*       __restrict__ outh)
{
    const int tid = threadIdx.x;
    const int m = tid >> 4;
    const int o = tid & 15;
    int node = blockIdx.x * 16 + m;
    const bool valid = node < NNODES;
    if (!valid) node = NNODES - 1;

    float2 fa[4];
    {
        uint4 u = ((const uint4*)(z + (size_t)node * DIM))[o];
        const __half2* h = (const __half2*)&u;
        #pragma unroll
        for (int j = 0; j < 4; j++) fa[j] = __half22float2(h[j]);
    }

    const int4* nrow = (const int4*)(nb + node * SAMP);
    #pragma unroll
    for (int sp = 0; sp < 4; sp++) {
        int4 id = nrow[sp];
        uint4 ua = ((const uint4*)(z + (size_t)id.x * DIM))[o];
        uint4 ub = ((const uint4*)(z + (size_t)id.y * DIM))[o];
        uint4 uc = ((const uint4*)(z + (size_t)id.z * DIM))[o];
        uint4 ud = ((const uint4*)(z + (size_t)id.w * DIM))[o];
        const __half2* ha = (const __half2*)&ua;
        const __half2* hb = (const __half2*)&ub;
        const __half2* hc = (const __half2*)&uc;
        const __half2* hd = (const __half2*)&ud;
        #pragma unroll
        for (int j = 0; j < 4; j++) {
            __half2 t = __hadd2(__hadd2(ha[j], hb[j]), __hadd2(hc[j], hd[j]));
            float2 f = __half22float2(t);
            fa[j].x += f.x;
            fa[j].y += f.y;
        }
    }

    const float inv17 = 1.0f / (float)(SAMP + 1);
    float ss = 0.0f;
    #pragma unroll
    for (int j = 0; j < 4; j++) {
        float2 v = fa[j];
        v.x = fmaxf(v.x * inv17, 0.0f);
        v.y = fmaxf(v.y * inv17, 0.0f);
        fa[j] = v;
        ss += v.x * v.x + v.y * v.y;
    }
    ss += __shfl_xor_sync(0xffffffffu, ss, 1);
    ss += __shfl_xor_sync(0xffffffffu, ss, 2);
    ss += __shfl_xor_sync(0xffffffffu, ss, 4);
    ss += __shfl_xor_sync(0xffffffffu, ss, 8);

    const float inv = 1.0f / fmaxf(sqrtf(ss), 1e-12f);
    if (valid) {
        __half2 h[4];
        #pragma unroll
        for (int j = 0; j < 4; j++)
            h[j] = __float22half2_rn(make_float2(fa[j].x * inv, fa[j].y * inv));
        ((uint4*)(outh + (size_t)node * DIM))[o] =
            make_uint4(*(unsigned*)&h[0], *(unsigned*)&h[1],
                       *(unsigned*)&h[2], *(unsigned*)&h[3]);
    }
}

// ---------------------------------------------------------------------------
// fused layer 2: out[n] = normalize(relu( (agg(x1)/17) @ w2^T ))  (fp32 out)
// Phase 1: gather 128 nodes -> agg tile fp16 in smem (swizzled for ldmatrix)
// Phase 2: MMA from smem (paired W)
// Phase 3: relu + warp-local row norms (shfl over the 4 c-lanes)
// Phase 4: fp32 epilogue smem -> 512B-contiguous STG.128
// ---------------------------------------------------------------------------
#define FEPI_STRIDE 528        // fp32 epilogue row stride (bytes)
#define FEPI_BYTES  (8 * 16 * FEPI_STRIDE)   // 67584 B (overlays WP+AGG)

__global__ __launch_bounds__(256, 3)
void fused_layer2(const __half* __restrict__ x,
                  const int*    __restrict__ nb,
                  const float*  __restrict__ W,      // [128,128]
                  float*        __restrict__ out, int nrows)
{
    constexpr int P  = DIM / 4;   // 32
    constexpr int PM = P - 1;
    constexpr int CH = DIM / 8;   // 16

    extern __shared__ char smraw[];
    uint2* WP  = (uint2*)smraw;                       // 32 KB
    uint4* AGG = (uint4*)(smraw + 32768);             // 32 KB [128][16] swizzled
    char*  EPI = smraw;                               // overlay after MMA

    const int tid = threadIdx.x;
    const int rowbase = blockIdx.x * 128;

    // ---- Stage W paired ---------------------------------------------------
    for (int idx = tid; idx < DIM * P; idx += 256) {
        int n = idx / P, p = idx % P;
        int ks = p >> 2, c = p & 3;
        const float* row = W + n * DIM + ks * 16 + 2 * c;
        __half2 h0 = __float22half2_rn(*(const float2*)&row[0]);
        __half2 h1 = __float22half2_rn(*(const float2*)&row[8]);
        int sp = p ^ (((n & 7) << 2) & PM);
        WP[n * P + sp] = make_uint2(*(unsigned*)&h0, *(unsigned*)&h1);
    }

    // ---- Phase 1: gather 128 nodes (16 lanes/node, 8 passes) --------------
    {
        const int m = tid >> 4, o = tid & 15;
        const float inv17 = 1.0f / (float)(SAMP + 1);
        #pragma unroll 1
        for (int pass = 0; pass < 8; pass++) {
            int r = pass * 16 + m;
            int node = rowbase + r;
            if (node >= nrows) node = nrows - 1;

            float2 fa[4];
            {
                uint4 u = ((const uint4*)(x + (size_t)node * DIM))[o];
                const __half2* h = (const __half2*)&u;
                #pragma unroll
                for (int j = 0; j < 4; j++) fa[j] = __half22float2(h[j]);
            }
            const int4* nrow4 = (const int4*)(nb + (size_t)node * SAMP);
            #pragma unroll
            for (int sp = 0; sp < 4; sp++) {
                int4 id = nrow4[sp];
                uint4 ua = ((const uint4*)(x + (size_t)id.x * DIM))[o];
                uint4 ub = ((const uint4*)(x + (size_t)id.y * DIM))[o];
                uint4 uc = ((const uint4*)(x + (size_t)id.z * DIM))[o];
                uint4 ud = ((const uint4*)(x + (size_t)id.w * DIM))[o];
                const __half2* ha = (const __half2*)&ua;
                const __half2* hb = (const __half2*)&ub;
                const __half2* hc = (const __half2*)&uc;
                const __half2* hd = (const __half2*)&ud;
                #pragma unroll
                for (int j = 0; j < 4; j++) {
                    __half2 t = __hadd2(__hadd2(ha[j], hb[j]),
                                        __hadd2(hc[j], hd[j]));
                    float2 f = __half22float2(t);
                    fa[j].x += f.x;
                    fa[j].y += f.y;
                }
            }
            __half2 h[4];
            #pragma unroll
            for (int j = 0; j < 4; j++)
                h[j] = __float22half2_rn(make_float2(fa[j].x * inv17,
                                                     fa[j].y * inv17));
            AGG[r * CH + (o ^ (r & 7))] =
                make_uint4(*(unsigned*)&h[0], *(unsigned*)&h[1],
                           *(unsigned*)&h[2], *(unsigned*)&h[3]);
        }
    }
    __syncthreads();

    // ---- Phase 2: MMA -----------------------------------------------------
    const int warp = tid >> 5, lane = tid & 31;
    const int g = lane >> 2, c = lane & 3;
    const int slab = warp * 16;
    const int lrow = slab + (lane & 7) + ((lane >> 3) & 1) * 8;
    const int lhi  = lane >> 4;
    const int lsw  = lrow & 7;
    const unsigned as_u32 =
        (unsigned)__cvta_generic_to_shared(AGG) + (unsigned)(lrow * CH) * 16u;

    float d[16][4];
    #pragma unroll
    for (int nt = 0; nt < 16; nt++)
        #pragma unroll
        for (int q = 0; q < 4; q++) d[nt][q] = 0.0f;

    const int gswm = (g << 2) & PM;

    #pragma unroll
    for (int ks = 0; ks < 8; ks++) {
        unsigned a0, a1, a2, a3;
        unsigned ad = as_u32 + (unsigned)(((ks * 2 + lhi) ^ lsw) * 16);
        LDSM_X4(a0, a1, a2, a3, ad);
        const int col = (ks * 4 + c) ^ gswm;
        #pragma unroll
        for (int nt = 0; nt < 16; nt++) {
            uint2 b = WP[(nt * 8 + g) * P + col];
            MMA_F16(d[nt], a0, a1, a2, a3, b.x, b.y);
        }
    }
    __syncthreads();      // WP/AGG dead; EPI overlay begins

    // ---- Phase 3: relu + row norms ---------------------------------------
    float ss0 = 0.0f, ss1 = 0.0f;
    #pragma unroll
    for (int nt = 0; nt < 16; nt++) {
        float v0 = fmaxf(d[nt][0], 0.0f);
        float v1 = fmaxf(d[nt][1], 0.0f);
        float v2 = fmaxf(d[nt][2], 0.0f);
        float v3 = fmaxf(d[nt][3], 0.0f);
        d[nt][0] = v0; d[nt][1] = v1; d[nt][2] = v2; d[nt][3] = v3;
        ss0 += v0 * v0 + v1 * v1;
        ss1 += v2 * v2 + v3 * v3;
    }
    ss0 += __shfl_xor_sync(0xffffffffu, ss0, 1);
    ss0 += __shfl_xor_sync(0xffffffffu, ss0, 2);
    ss1 += __shfl_xor_sync(0xffffffffu, ss1, 1);
    ss1 += __shfl_xor_sync(0xffffffffu, ss1, 2);
    const float inv0 = 1.0f / fmaxf(sqrtf(ss0), 1e-12f);
    const float inv1 = 1.0f / fmaxf(sqrtf(ss1), 1e-12f);

    // ---- Phase 4: fp32 epilogue ------------------------------------------
    char* myepi = EPI + warp * (16 * FEPI_STRIDE);
    #pragma unroll
    for (int nt = 0; nt < 16; nt++) {
        *(float2*)(myepi + g * FEPI_STRIDE + nt * 32 + 8 * c) =
            make_float2(d[nt][0] * inv0, d[nt][1] * inv0);
        *(float2*)(myepi + (g + 8) * FEPI_STRIDE + nt * 32 + 8 * c) =
            make_float2(d[nt][2] * inv1, d[nt][3] * inv1);
    }
    __syncwarp();
    #pragma unroll
    for (int i = 0; i < 16; i++) {
        uint4 v = *(const uint4*)(myepi + i * FEPI_STRIDE + lane * 16);
        int gr = rowbase + slab + i;
        if (gr < nrows)
            *(uint4*)((char*)(out + (size_t)gr * DIM) + lane * 16) = v;
    }
}

// ---------------------------------------------------------------------------
extern "C" void kernel_launch(void* const* d_in, const int* in_sizes, int n_in,
                              void* d_out, int out_size)
{
    const float* feat = (const float*)d_in[0];   // [N, 64]
    const float* wf   = (const float*)d_in[1];   // [128, 64]
    const float* w1   = (const float*)d_in[2];   // [128, 128]
    const float* w2   = (const float*)d_in[3];   // [128, 128]
    const int*   n1   = (const int*)d_in[4];     // [N, 16]
    const int*   n2   = (const int*)d_in[5];     // [N, 16]
    float* out = (float*)d_out;                  // [N, 128]

    void *pz = nullptr, *px1 = nullptr, *pwc = nullptr;
    cudaGetSymbolAddress(&pz, g_z);
    cudaGetSymbolAddress(&px1, g_x1h);
    cudaGetSymbolAddress(&pwc, g_wc);
    __half* z   = (__half*)pz;
    __half* x1h = (__half*)px1;
    float*  wc  = (float*)pwc;

    const size_t SM64   = (size_t)DIM * (FIN / 4) * sizeof(uint2) + EPI_BYTES; // ~50 KB
    const size_t SMFUSE = FEPI_BYTES;                                          // 67.6 KB
    cudaFuncSetAttribute((const void*)gemm_tc<FIN>,
                         cudaFuncAttributeMaxDynamicSharedMemorySize, (int)SM64);
    cudaFuncSetAttribute((const void*)fused_layer2,
                         cudaFuncAttributeMaxDynamicSharedMemorySize, (int)SMFUSE);

    const int gemm_grid = (NNODES + 127) / 128;     // 782
    const int gn_grid   = (NNODES + 15) / 16;       // 6250

    // wc = w1 @ wf  (folds layer-1 GEMM into the feature GEMM)
    wc_kernel<<<32, 256>>>(w1, wf, wc);
    // z1 = feat @ wc^T   (fp16 out)
    gemm_tc<FIN><<<gemm_grid, 256, SM64>>>(feat, wc, z, NNODES);
    // x1 = normalize(relu(agg(z1)/17))  -> fp16
    gathernorm<<<gn_grid, 256>>>(z, n1, x1h);
    // out = normalize(relu((agg(x1)/17) @ w2^T))   (fused, fp32 out)
    fused_layer2<<<gemm_grid, 256, SMFUSE>>>(x1h, n2, w2, out, NNODES);
}

// round 16
// speedup vs baseline: 1.0670x; 1.0670x over previous
#include <cuda_runtime.h>
#include <cuda_fp16.h>

#define NNODES 100000
#define DIM 128
#define FIN 64
#define SAMP 16

// Scratch (module-load allocated; no runtime alloc)
__device__ __half g_z  [(size_t)NNODES * DIM];   // pre-aggregation embeddings
__device__ __half g_x1h[(size_t)NNODES * DIM];   // layer-1 output (fp16)
__device__ float  g_wc [DIM * FIN];              // folded w1 @ wf

// ---------------------------------------------------------------------------
// wc = w1 @ wf   [128,128]@[128,64] -> [128,64]
// ---------------------------------------------------------------------------
__global__ void wc_kernel(const float* __restrict__ w1,
                          const float* __restrict__ wf,
                          float* __restrict__ wc)
{
    int idx = blockIdx.x * 256 + threadIdx.x;      // 8192 outputs
    if (idx >= DIM * FIN) return;
    int i = idx >> 6, j = idx & 63;
    float s = 0.0f;
    #pragma unroll 8
    for (int t = 0; t < DIM; t++)
        s = fmaf(w1[i * DIM + t], wf[t * FIN + j], s);
    wc[i * FIN + j] = s;
}

// ---------------------------------------------------------------------------
// PTX helpers
// ---------------------------------------------------------------------------
#define MMA_F16(D, A0,A1,A2,A3, B0,B1)                                       \
    asm volatile("mma.sync.aligned.m16n8k16.row.col.f32.f16.f16.f32 "        \
                 "{%0,%1,%2,%3},{%4,%5,%6,%7},{%8,%9},{%0,%1,%2,%3};"        \
                 : "+f"(D[0]), "+f"(D[1]), "+f"(D[2]), "+f"(D[3])            \
                 : "r"(A0), "r"(A1), "r"(A2), "r"(A3), "r"(B0), "r"(B1))

#define LDSM_X4(R0,R1,R2,R3, ADDR)                                           \
    asm volatile("ldmatrix.sync.aligned.m8n8.x4.shared.b16 {%0,%1,%2,%3}, [%4];" \
                 : "=r"(R0), "=r"(R1), "=r"(R2), "=r"(R3) : "r"(ADDR))

#define CP_ASYNC16(DST_U32, SRC)                                             \
    asm volatile("cp.async.cg.shared.global [%0], [%1], 16;"                 \
                 :: "r"(DST_U32), "l"(SRC))
#define CP_ASYNC_FLUSH()                                                     \
    asm volatile("cp.async.commit_group;\n\tcp.async.wait_group 0;" ::: "memory")

#define EPI_STRIDE 144          // fp16 half-row epilogue stride (bytes)

// ---------------------------------------------------------------------------
// N-split dense GEMM: C[nrows, nhalf*64 .. +64](fp16) = A[nrows,K] @ Wh^T
// gridDim = (rowtiles, 2). Per CTA: 128 rows x 64 cols, warp = m16 x n64.
// A staged via cp.async (fp16) / convert (fp32); ldmatrix fragments;
// paired-W LDS.64; epilogue overlays WP+AS. 256 thr, 4 CTAs/SM.
// ---------------------------------------------------------------------------
template<int K, bool AF32>
__global__ __launch_bounds__(256, 4)
void gemm_ns(const void* __restrict__ Av,
             const float* __restrict__ W,
             __half* __restrict__ C, int nrows)
{
    constexpr int P   = K / 4;
    constexpr int PM  = P - 1;
    constexpr int CH  = K / 8;
    constexpr int CHM = CH - 1;

    extern __shared__ char smraw[];
    uint2* WP  = (uint2*)smraw;                            // [64][P]
    uint4* AS  = (uint4*)(smraw + 64 * P * sizeof(uint2)); // [128][CH] swizzled
    char*  EPI = smraw;                                    // overlay after MMA

    const int tid = threadIdx.x;
    const int rowbase = blockIdx.x * 128;
    const int nhalf = blockIdx.y;                 // 0/1 -> output cols [0,64)/[64,128)

    // ---- Stage A tile [128, K] swizzled ----------------------------------
    if constexpr (AF32) {
        for (int idx = tid; idx < 128 * CH; idx += 256) {
            int r = idx / CH, ch = idx % CH;
            int gr = rowbase + r;
            if (gr >= nrows) gr = nrows - 1;
            const float* src = (const float*)Av + (size_t)gr * K + ch * 8;
            __half2 h0 = __float22half2_rn(*(const float2*)&src[0]);
            __half2 h1 = __float22half2_rn(*(const float2*)&src[2]);
            __half2 h2 = __float22half2_rn(*(const float2*)&src[4]);
            __half2 h3 = __float22half2_rn(*(const float2*)&src[6]);
            AS[r * CH + (ch ^ ((r & 7) & CHM))] =
                make_uint4(*(unsigned*)&h0, *(unsigned*)&h1,
                           *(unsigned*)&h2, *(unsigned*)&h3);
        }
    } else {
        const unsigned as_b = (unsigned)__cvta_generic_to_shared(AS);
        for (int idx = tid; idx < 128 * CH; idx += 256) {
            int r = idx / CH, ch = idx % CH;
            int gr = rowbase + r;
            if (gr >= nrows) gr = nrows - 1;
            const __half* src = (const __half*)Av + (size_t)gr * K + ch * 8;
            unsigned dst = as_b + (unsigned)(r * CH + (ch ^ ((r & 7) & CHM))) * 16u;
            CP_ASYNC16(dst, src);
        }
    }

    // ---- Stage W half [64, K] paired --------------------------------------
    for (int idx = tid; idx < 64 * P; idx += 256) {
        int n = idx / P, p = idx % P;
        int ks = p >> 2, c = p & 3;
        const float* row = W + (size_t)(nhalf * 64 + n) * K + ks * 16 + 2 * c;
        __half2 h0 = __float22half2_rn(*(const float2*)&row[0]);
        __half2 h1 = __float22half2_rn(*(const float2*)&row[8]);
        int sp = p ^ (((n & 7) << 2) & PM);
        WP[n * P + sp] = make_uint2(*(unsigned*)&h0, *(unsigned*)&h1);
    }

    if constexpr (!AF32) CP_ASYNC_FLUSH();
    __syncthreads();

    const int warp = tid >> 5, lane = tid & 31;
    const int g = lane >> 2, c = lane & 3;
    const int slab = warp * 16;

    const int lrow = slab + (lane & 7) + ((lane >> 3) & 1) * 8;
    const int lhi  = lane >> 4;
    const int lsw  = (lrow & 7) & CHM;
    const unsigned as_u32 =
        (unsigned)__cvta_generic_to_shared(AS) + (unsigned)(lrow * CH) * 16u;

    float d[8][4];
    #pragma unroll
    for (int nt = 0; nt < 8; nt++)
        #pragma unroll
        for (int q = 0; q < 4; q++) d[nt][q] = 0.0f;

    const int gswm = (g << 2) & PM;

    #pragma unroll
    for (int ks = 0; ks < K / 16; ks++) {
        unsigned a0, a1, a2, a3;
        unsigned ad = as_u32 + (unsigned)(((ks * 2 + lhi) ^ lsw) * 16);
        LDSM_X4(a0, a1, a2, a3, ad);
        const int col = (ks * 4 + c) ^ gswm;
        #pragma unroll
        for (int nt = 0; nt < 8; nt++) {
            uint2 b = WP[(nt * 8 + g) * P + col];
            MMA_F16(d[nt], a0, a1, a2, a3, b.x, b.y);
        }
    }
    __syncthreads();      // WP/AS dead; EPI overlay begins

    // ---- Epilogue: STS -> LDS.128 -> contiguous STG.128 -------------------
    char* myepi = EPI + warp * (16 * EPI_STRIDE);
    #pragma unroll
    for (int nt = 0; nt < 8; nt++) {
        __half2 h0 = __float22half2_rn(make_float2(d[nt][0], d[nt][1]));
        __half2 h1 = __float22half2_rn(make_float2(d[nt][2], d[nt][3]));
        *(__half2*)(myepi + g * EPI_STRIDE + nt * 16 + 4 * c) = h0;
        *(__half2*)(myepi + (g + 8) * EPI_STRIDE + nt * 16 + 4 * c) = h1;
    }
    __syncwarp();
    {
        const int rsub = lane >> 3;    // 0..3
        const int j    = lane & 7;     // 16B chunk within 128B half-row
        #pragma unroll
        for (int i = 0; i < 4; i++) {
            int r = i * 4 + rsub;
            uint4 v = *(const uint4*)(myepi + r * EPI_STRIDE + j * 16);
            int gr = rowbase + slab + r;
            if (gr < nrows)
                *(uint4*)((char*)(C + (size_t)gr * DIM) + nhalf * 128 + j * 16) = v;
        }
    }
}

// ---------------------------------------------------------------------------
// gathernorm: out[n] = normalize(relu((z[n] + sum_s z[nb[n,s]]) / 17))
// 16 lanes/node, lane o owns one 16B chunk (17 x LDG.128 per thread).
// Neighbors in 4 groups of 4: 2-level fp16 tree then one fp32 accumulate.
// ---------------------------------------------------------------------------
template<bool HALF_OUT>
__global__ __launch_bounds__(256)
void gathernorm(const __half* __restrict__ z,
                const int*    __restrict__ nb,
                void*         __restrict__ outv)
{
    const int tid = threadIdx.x;
    const int m = tid >> 4;
    const int o = tid & 15;
    int node = blockIdx.x * 16 + m;
    const bool valid = node < NNODES;
    if (!valid) node = NNODES - 1;

    float2 fa[4];
    {
        uint4 u = ((const uint4*)(z + (size_t)node * DIM))[o];
        const __half2* h = (const __half2*)&u;
        #pragma unroll
        for (int j = 0; j < 4; j++) fa[j] = __half22float2(h[j]);
    }

    const int4* nrow = (const int4*)(nb + node * SAMP);
    #pragma unroll
    for (int sp = 0; sp < 4; sp++) {
        int4 id = nrow[sp];
        uint4 ua = ((const uint4*)(z + (size_t)id.x * DIM))[o];
        uint4 ub = ((const uint4*)(z + (size_t)id.y * DIM))[o];
        uint4 uc = ((const uint4*)(z + (size_t)id.z * DIM))[o];
        uint4 ud = ((const uint4*)(z + (size_t)id.w * DIM))[o];
        const __half2* ha = (const __half2*)&ua;
        const __half2* hb = (const __half2*)&ub;
        const __half2* hc = (const __half2*)&uc;
        const __half2* hd = (const __half2*)&ud;
        #pragma unroll
        for (int j = 0; j < 4; j++) {
            __half2 t = __hadd2(__hadd2(ha[j], hb[j]), __hadd2(hc[j], hd[j]));
            float2 f = __half22float2(t);
            fa[j].x += f.x;
            fa[j].y += f.y;
        }
    }

    const float inv17 = 1.0f / (float)(SAMP + 1);
    float ss = 0.0f;
    #pragma unroll
    for (int j = 0; j < 4; j++) {
        float2 v = fa[j];
        v.x = fmaxf(v.x * inv17, 0.0f);
        v.y = fmaxf(v.y * inv17, 0.0f);
        fa[j] = v;
        ss += v.x * v.x + v.y * v.y;
    }
    ss += __shfl_xor_sync(0xffffffffu, ss, 1);
    ss += __shfl_xor_sync(0xffffffffu, ss, 2);
    ss += __shfl_xor_sync(0xffffffffu, ss, 4);
    ss += __shfl_xor_sync(0xffffffffu, ss, 8);

    const float inv = 1.0f / fmaxf(sqrtf(ss), 1e-12f);
    if (valid) {
        if (HALF_OUT) {
            __half2 h[4];
            #pragma unroll
            for (int j = 0; j < 4; j++)
                h[j] = __float22half2_rn(make_float2(fa[j].x * inv, fa[j].y * inv));
            ((uint4*)((__half*)outv + (size_t)node * DIM))[o] =
                make_uint4(*(unsigned*)&h[0], *(unsigned*)&h[1],
                           *(unsigned*)&h[2], *(unsigned*)&h[3]);
        } else {
            float4* orow = (float4*)((float*)outv + (size_t)node * DIM);
            orow[2 * o]     = make_float4(fa[0].x * inv, fa[0].y * inv,
                                          fa[1].x * inv, fa[1].y * inv);
            orow[2 * o + 1] = make_float4(fa[2].x * inv, fa[2].y * inv,
                                          fa[3].x * inv, fa[3].y * inv);
        }
    }
}

// ---------------------------------------------------------------------------
extern "C" void kernel_launch(void* const* d_in, const int* in_sizes, int n_in,
                              void* d_out, int out_size)
{
    const float* feat = (const float*)d_in[0];   // [N, 64]
    const float* wf   = (const float*)d_in[1];   // [128, 64]
    const float* w1   = (const float*)d_in[2];   // [128, 128]
    const float* w2   = (const float*)d_in[3];   // [128, 128]
    const int*   n1   = (const int*)d_in[4];     // [N, 16]
    const int*   n2   = (const int*)d_in[5];     // [N, 16]
    float* out = (float*)d_out;                  // [N, 128]

    void *pz = nullptr, *px1 = nullptr, *pwc = nullptr;
    cudaGetSymbolAddress(&pz, g_z);
    cudaGetSymbolAddress(&px1, g_x1h);
    cudaGetSymbolAddress(&pwc, g_wc);
    __half* z   = (__half*)pz;
    __half* x1h = (__half*)px1;
    float*  wc  = (float*)pwc;

    // smem: W half + A tile (epilogue overlays)
    const size_t SM64  = 64 * (FIN / 4) * sizeof(uint2) + 128 * (FIN / 8) * 16;  // 24 KB
    const size_t SM128 = 64 * (DIM / 4) * sizeof(uint2) + 128 * (DIM / 8) * 16;  // 48 KB
    cudaFuncSetAttribute((const void*)gemm_ns<FIN, true>,
                         cudaFuncAttributeMaxDynamicSharedMemorySize, (int)SM64);
    cudaFuncSetAttribute((const void*)gemm_ns<DIM, false>,
                         cudaFuncAttributeMaxDynamicSharedMemorySize, (int)SM128);

    const dim3 gemm_grid((NNODES + 127) / 128, 2);  // (782, 2)
    const int  gn_grid = (NNODES + 15) / 16;        // 6250

    // wc = w1 @ wf  (folds layer-1 GEMM into the feature GEMM)
    wc_kernel<<<32, 256>>>(w1, wf, wc);
    // z1 = feat @ wc^T   (fp16 out)
    gemm_ns<FIN, true><<<gemm_grid, 256, SM64>>>(feat, wc, z, NNODES);
    // x1 = normalize(relu(agg(z1)/17))  -> fp16
    gathernorm<true><<<gn_grid, 256>>>(z, n1, x1h);
    // z2 = x1 @ w2^T     (fp16 out)
    gemm_ns<DIM, false><<<gemm_grid, 256, SM128>>>(x1h, w2, z, NNODES);
    // out = normalize(relu(agg(z2)/17)) -> fp32
    gathernorm<false><<<gn_grid, 256>>>(z, n2, out);
}